// round 2
// baseline (speedup 1.0000x reference)
#include <cuda_runtime.h>
#include <cstdint>

#define N_CELL 200000
#define N_WELL 2000
#define E_CC   1200000
#define E_CW   200000
#define CF     16
#define WF     8
#define H      128
#define OUT    75
#define WPB    8

// ---------------- device scratch ----------------
__device__ __align__(16) float g_aggx[(size_t)N_CELL * CF]; // sum of x over in-edges (active cells)
__device__ int      g_cnt[N_CELL];                          // in-degree
__device__ unsigned g_bm[(N_CELL + 31) / 32];               // active-cell bitmap
__device__ __align__(16) float g_U[N_WELL * CF];            // sum of aggx[s]/c[s] per well
__device__ __align__(16) float g_V[N_WELL * CF];            // sum of x[s] per well
__device__ float    g_beta[N_WELL];                         // sum of 1{c[s]>0}
__device__ int      g_cw[N_WELL];                           // well edge count

__device__ __forceinline__ void red4(float* p, float a, float b, float c, float d) {
    asm volatile("red.global.add.v4.f32 [%0], {%1,%2,%3,%4};"
                 :: "l"(p), "f"(a), "f"(b), "f"(c), "f"(d) : "memory");
}

// ---------------- K1: zero state ----------------
__global__ void k_init() {
    int i = blockIdx.x * blockDim.x + threadIdx.x;
    if (i < N_CELL * CF) g_aggx[i] = 0.f;
    if (i < N_CELL)      g_cnt[i]  = 0;
    if (i < (N_CELL + 31) / 32) g_bm[i] = 0u;
    if (i < N_WELL * CF) { g_U[i] = 0.f; g_V[i] = 0.f; }
    if (i < N_WELL)      { g_beta[i] = 0.f; g_cw[i] = 0; }
}

// ---------------- K2: mark active cells ----------------
__global__ void k_mark(const int* __restrict__ ews) {
    int e = blockIdx.x * blockDim.x + threadIdx.x;
    if (e >= E_CW) return;
    int s = __ldg(&ews[e]);
    atomicOr(&g_bm[s >> 5], 1u << (s & 31));
}

// ---------------- K3: scan cell-cell edges, accumulate raw x into active dsts ----
__global__ void k_cc(const int* __restrict__ ei, const float* __restrict__ x) {
    int e = blockIdx.x * blockDim.x + threadIdx.x;
    if (e >= E_CC) return;
    int d = __ldg(&ei[E_CC + e]);                // row 1 = dst
    if (!((g_bm[d >> 5] >> (d & 31)) & 1u)) return;
    int s = __ldg(&ei[e]);                       // row 0 = src
    const float4* xp = (const float4*)(x + (size_t)s * CF);
    float* ap = g_aggx + (size_t)d * CF;
    float4 v0 = __ldg(xp + 0), v1 = __ldg(xp + 1), v2 = __ldg(xp + 2), v3 = __ldg(xp + 3);
    red4(ap + 0,  v0.x, v0.y, v0.z, v0.w);
    red4(ap + 4,  v1.x, v1.y, v1.z, v1.w);
    red4(ap + 8,  v2.x, v2.y, v2.z, v2.w);
    red4(ap + 12, v3.x, v3.y, v3.z, v3.w);
    atomicAdd(&g_cnt[d], 1);
}

// ---------------- K4: scan cell-well edges, accumulate U,V,beta,cnt per well ----
__global__ void k_cw(const int* __restrict__ ews, const int* __restrict__ ewd,
                     const float* __restrict__ x) {
    int e = blockIdx.x * blockDim.x + threadIdx.x;
    if (e >= E_CW) return;
    int s = __ldg(&ews[e]);
    int w = __ldg(&ewd[e]);
    int c = g_cnt[s];
    float inv = 1.f / fmaxf((float)c, 1.f);
    const float4* ap = (const float4*)(g_aggx + (size_t)s * CF);
    const float4* xp = (const float4*)(x + (size_t)s * CF);
    float* U = g_U + w * CF;
    float* V = g_V + w * CF;
    float4 a0 = ap[0], a1 = ap[1], a2 = ap[2], a3 = ap[3];
    red4(U + 0,  a0.x * inv, a0.y * inv, a0.z * inv, a0.w * inv);
    red4(U + 4,  a1.x * inv, a1.y * inv, a1.z * inv, a1.w * inv);
    red4(U + 8,  a2.x * inv, a2.y * inv, a2.z * inv, a2.w * inv);
    red4(U + 12, a3.x * inv, a3.y * inv, a3.z * inv, a3.w * inv);
    float4 b0 = __ldg(xp + 0), b1 = __ldg(xp + 1), b2 = __ldg(xp + 2), b3 = __ldg(xp + 3);
    red4(V + 0,  b0.x, b0.y, b0.z, b0.w);
    red4(V + 4,  b1.x, b1.y, b1.z, b1.w);
    red4(V + 8,  b2.x, b2.y, b2.z, b2.w);
    red4(V + 12, b3.x, b3.y, b3.z, b3.w);
    atomicAdd(&g_beta[w], (c > 0) ? 1.f : 0.f);
    atomicAdd(&g_cw[w], 1);
}

// ---------------- K5: per-well head (8 wells per block) ----------------
// mean(agg_c) = (U/cnt)@W_cell + (beta/cnt)*b_cell
// mean(h0)    = (V/cnt)@W_cell + b_cell
// agg_w = mean(agg_c)@Wl_cc + bl_cc + mean(h0)@Wr_cc   (0 if cnt==0)
// well_h1 = agg_w@Wl_cw + bl_cw + (well_x@W_well + b_well)@Wr_cw
// out = relu(well_h1@Wm1 + bm1)@Wm2 + bm2
__global__ void __launch_bounds__(H) k_well(
    const float* __restrict__ well_x,
    const float* __restrict__ W_cell, const float* __restrict__ b_cell,
    const float* __restrict__ Wl_cc, const float* __restrict__ bl_cc,
    const float* __restrict__ Wr_cc,
    const float* __restrict__ W_well, const float* __restrict__ b_well,
    const float* __restrict__ Wl_cw, const float* __restrict__ bl_cw,
    const float* __restrict__ Wr_cw,
    const float* __restrict__ Wm1, const float* __restrict__ bm1,
    const float* __restrict__ Wm2, const float* __restrict__ bm2,
    float* __restrict__ out)
{
    __shared__ __align__(16) float sA[H][WPB];  // P -> h2
    __shared__ __align__(16) float sB[H][WPB];  // Q -> m
    __shared__ __align__(16) float sC[H][WPB];  // aggw
    __shared__ __align__(16) float sD[H][WPB];  // wh
    __shared__ float sU[WPB][CF], sV[WPB][CF], sWX[WPB][WF];
    __shared__ float sbn[WPB], sinv[WPB];
    __shared__ int scw[WPB];

    int h  = threadIdx.x;
    int w0 = blockIdx.x * WPB;

    if (h < WPB) {
        int c = g_cw[w0 + h];
        scw[h] = c;
        float iv = 1.f / fmaxf((float)c, 1.f);
        sinv[h] = iv;
        sbn[h]  = g_beta[w0 + h] * iv;
    }
    __syncthreads();
    if (h < WPB * CF) {
        int t = h >> 4, j = h & 15;
        float iv = sinv[t];
        sU[t][j] = g_U[(w0 + t) * CF + j] * iv;
        sV[t][j] = g_V[(w0 + t) * CF + j] * iv;
    }
    if (h < WPB * WF) {
        int t = h >> 3, j = h & 7;
        sWX[t][j] = __ldg(&well_x[(w0 + t) * WF + j]);
    }
    __syncthreads();

    // stage1: P, Q, wh
    {
        float Wc[CF];
#pragma unroll
        for (int j = 0; j < CF; j++) Wc[j] = __ldg(&W_cell[j * H + h]);
        float bc = __ldg(&b_cell[h]);
#pragma unroll
        for (int t = 0; t < WPB; t++) {
            float p = sbn[t] * bc, q = bc;
#pragma unroll
            for (int j = 0; j < CF; j++) { p += sU[t][j] * Wc[j]; q += sV[t][j] * Wc[j]; }
            sA[h][t] = p;
            sB[h][t] = q;
        }
        float Ww[WF];
#pragma unroll
        for (int j = 0; j < WF; j++) Ww[j] = __ldg(&W_well[j * H + h]);
        float bw = __ldg(&b_well[h]);
#pragma unroll
        for (int t = 0; t < WPB; t++) {
            float v = bw;
#pragma unroll
            for (int j = 0; j < WF; j++) v += sWX[t][j] * Ww[j];
            sD[h][t] = v;
        }
    }
    __syncthreads();

    // stage2: aggw = P@Wl_cc + bl_cc + Q@Wr_cc -> sC
    {
        float acc[WPB];
        float blv = __ldg(&bl_cc[h]);
#pragma unroll
        for (int t = 0; t < WPB; t++) acc[t] = blv;
#pragma unroll 4
        for (int k = 0; k < H; k++) {
            float w1 = __ldg(&Wl_cc[k * H + h]);
            float w2 = __ldg(&Wr_cc[k * H + h]);
            float4 p0 = *(const float4*)&sA[k][0];
            float4 p1 = *(const float4*)&sA[k][4];
            float4 q0 = *(const float4*)&sB[k][0];
            float4 q1 = *(const float4*)&sB[k][4];
            acc[0] += p0.x * w1 + q0.x * w2;  acc[1] += p0.y * w1 + q0.y * w2;
            acc[2] += p0.z * w1 + q0.z * w2;  acc[3] += p0.w * w1 + q0.w * w2;
            acc[4] += p1.x * w1 + q1.x * w2;  acc[5] += p1.y * w1 + q1.y * w2;
            acc[6] += p1.z * w1 + q1.z * w2;  acc[7] += p1.w * w1 + q1.w * w2;
        }
#pragma unroll
        for (int t = 0; t < WPB; t++) sC[h][t] = (scw[t] > 0) ? acc[t] : 0.f;
    }
    __syncthreads();

    // stage3: h2 = aggw@Wl_cw + bl_cw + wh@Wr_cw -> sA
    {
        float acc[WPB];
        float blv = __ldg(&bl_cw[h]);
#pragma unroll
        for (int t = 0; t < WPB; t++) acc[t] = blv;
#pragma unroll 4
        for (int k = 0; k < H; k++) {
            float w1 = __ldg(&Wl_cw[k * H + h]);
            float w2 = __ldg(&Wr_cw[k * H + h]);
            float4 p0 = *(const float4*)&sC[k][0];
            float4 p1 = *(const float4*)&sC[k][4];
            float4 q0 = *(const float4*)&sD[k][0];
            float4 q1 = *(const float4*)&sD[k][4];
            acc[0] += p0.x * w1 + q0.x * w2;  acc[1] += p0.y * w1 + q0.y * w2;
            acc[2] += p0.z * w1 + q0.z * w2;  acc[3] += p0.w * w1 + q0.w * w2;
            acc[4] += p1.x * w1 + q1.x * w2;  acc[5] += p1.y * w1 + q1.y * w2;
            acc[6] += p1.z * w1 + q1.z * w2;  acc[7] += p1.w * w1 + q1.w * w2;
        }
        __syncthreads();   // all threads done reading sA(P) before overwrite
#pragma unroll
        for (int t = 0; t < WPB; t++) sA[h][t] = acc[t];
    }
    __syncthreads();

    // stage4: m = relu(h2@Wm1 + bm1) -> sB
    {
        float acc[WPB];
        float bv = __ldg(&bm1[h]);
#pragma unroll
        for (int t = 0; t < WPB; t++) acc[t] = bv;
#pragma unroll 4
        for (int k = 0; k < H; k++) {
            float wm = __ldg(&Wm1[k * H + h]);
            float4 p0 = *(const float4*)&sA[k][0];
            float4 p1 = *(const float4*)&sA[k][4];
            acc[0] += p0.x * wm;  acc[1] += p0.y * wm;
            acc[2] += p0.z * wm;  acc[3] += p0.w * wm;
            acc[4] += p1.x * wm;  acc[5] += p1.y * wm;
            acc[6] += p1.z * wm;  acc[7] += p1.w * wm;
        }
        __syncthreads();   // done reading sB(Q) long ago; protect sA readers
#pragma unroll
        for (int t = 0; t < WPB; t++) sB[h][t] = fmaxf(acc[t], 0.f);
    }
    __syncthreads();

    // stage5: out = m@Wm2 + bm2
    if (h < OUT) {
        float acc[WPB];
        float bv = __ldg(&bm2[h]);
#pragma unroll
        for (int t = 0; t < WPB; t++) acc[t] = bv;
#pragma unroll 4
        for (int k = 0; k < H; k++) {
            float wm = __ldg(&Wm2[k * OUT + h]);
            float4 p0 = *(const float4*)&sB[k][0];
            float4 p1 = *(const float4*)&sB[k][4];
            acc[0] += p0.x * wm;  acc[1] += p0.y * wm;
            acc[2] += p0.z * wm;  acc[3] += p0.w * wm;
            acc[4] += p1.x * wm;  acc[5] += p1.y * wm;
            acc[6] += p1.z * wm;  acc[7] += p1.w * wm;
        }
#pragma unroll
        for (int t = 0; t < WPB; t++) out[(w0 + t) * OUT + h] = acc[t];
    }
}

// ---------------- launch ----------------
extern "C" void kernel_launch(void* const* d_in, const int* in_sizes, int n_in,
                              void* d_out, int out_size)
{
    const float* cell_x  = (const float*)d_in[0];
    const float* well_x  = (const float*)d_in[1];
    const int*   ei_cell = (const int*)  d_in[2];
    const int*   ews     = (const int*)  d_in[3];
    const int*   ewd     = (const int*)  d_in[4];
    const float* W_cell  = (const float*)d_in[5];
    const float* b_cell  = (const float*)d_in[6];
    const float* W_well  = (const float*)d_in[7];
    const float* b_well  = (const float*)d_in[8];
    const float* Wl_cc   = (const float*)d_in[9];
    const float* bl_cc   = (const float*)d_in[10];
    const float* Wr_cc   = (const float*)d_in[11];
    const float* Wl_cw   = (const float*)d_in[12];
    const float* bl_cw   = (const float*)d_in[13];
    const float* Wr_cw   = (const float*)d_in[14];
    const float* W_m1    = (const float*)d_in[15];
    const float* b_m1    = (const float*)d_in[16];
    const float* W_m2    = (const float*)d_in[17];
    const float* b_m2    = (const float*)d_in[18];
    float* out = (float*)d_out;

    k_init<<<(N_CELL * CF + 255) / 256, 256>>>();
    k_mark<<<(E_CW + 255) / 256, 256>>>(ews);
    k_cc<<<(E_CC + 255) / 256, 256>>>(ei_cell, cell_x);
    k_cw<<<(E_CW + 255) / 256, 256>>>(ews, ewd, cell_x);
    k_well<<<N_WELL / WPB, H>>>(well_x, W_cell, b_cell,
                                Wl_cc, bl_cc, Wr_cc,
                                W_well, b_well,
                                Wl_cw, bl_cw, Wr_cw,
                                W_m1, b_m1, W_m2, b_m2, out);
}

// round 3
// speedup vs baseline: 1.3036x; 1.3036x over previous
#include <cuda_runtime.h>
#include <cstdint>

#define N_CELL 200000
#define N_WELL 2000
#define E_CC   1200000
#define E_CW   200000
#define CF     16
#define WF     8
#define H      128
#define OUT    75
#define WPB    8
#define R      16          // replicas for well accumulators

// ---------------- device scratch ----------------
__device__ __align__(16) float g_aggx[(size_t)N_CELL * CF];
__device__ int      g_cnt[N_CELL];
__device__ unsigned g_bm[(N_CELL + 31) / 32];
__device__ __align__(16) float g_Ur[(size_t)R * N_WELL * CF];
__device__ __align__(16) float g_Vr[(size_t)R * N_WELL * CF];
__device__ __align__(16) float g_meta[(size_t)R * N_WELL * 4];   // {mask_sum(beta), count, 0, 0}

// fused-weight scratch
__device__ float g_B[H * H];      // Wl_cw @ Wm1
__device__ float g_D[H * H];      // Wr_cw @ Wm1
__device__ float g_C1[CF * H];    // W_cell @ Wl_cc
__device__ float g_C2[CF * H];    // W_cell @ Wr_cc
__device__ float g_c3[H];         // b_cell @ Wl_cc
__device__ float g_c4[H];         // bl_cc + b_cell @ Wr_cc
__device__ float g_M1[CF * H];
__device__ float g_M2[CF * H];
__device__ float g_M3[WF * H];
__device__ float g_v1[H];
__device__ float g_v2[H];
__device__ float g_v3[H];

__device__ __forceinline__ void red4(float* p, float a, float b, float c, float d) {
    asm volatile("red.global.add.v4.f32 [%0], {%1,%2,%3,%4};"
                 :: "l"(p), "f"(a), "f"(b), "f"(c), "f"(d) : "memory");
}

// ---------------- K1: zero state ----------------
__global__ void k_init() {
    int i = blockIdx.x * blockDim.x + threadIdx.x;
    if (i < N_CELL * CF) g_aggx[i] = 0.f;
    if (i < N_CELL)      g_cnt[i]  = 0;
    if (i < (N_CELL + 31) / 32) g_bm[i] = 0u;
    if (i < R * N_WELL * CF) { g_Ur[i] = 0.f; g_Vr[i] = 0.f; }
    if (i < R * N_WELL * 4)  g_meta[i] = 0.f;
}

// ---------------- K2: mark active cells ----------------
__global__ void k_mark(const int* __restrict__ ews) {
    int e = blockIdx.x * blockDim.x + threadIdx.x;
    if (e >= E_CW) return;
    int s = __ldg(&ews[e]);
    atomicOr(&g_bm[s >> 5], 1u << (s & 31));
}

// ---------------- K3: scan cell-cell edges ----------------
__global__ void k_cc(const int* __restrict__ ei, const float* __restrict__ x) {
    int e = blockIdx.x * blockDim.x + threadIdx.x;
    if (e >= E_CC) return;
    int d = __ldg(&ei[E_CC + e]);
    if (!((g_bm[d >> 5] >> (d & 31)) & 1u)) return;
    int s = __ldg(&ei[e]);
    const float4* xp = (const float4*)(x + (size_t)s * CF);
    float* ap = g_aggx + (size_t)d * CF;
    float4 v0 = __ldg(xp + 0), v1 = __ldg(xp + 1), v2 = __ldg(xp + 2), v3 = __ldg(xp + 3);
    red4(ap + 0,  v0.x, v0.y, v0.z, v0.w);
    red4(ap + 4,  v1.x, v1.y, v1.z, v1.w);
    red4(ap + 8,  v2.x, v2.y, v2.z, v2.w);
    red4(ap + 12, v3.x, v3.y, v3.z, v3.w);
    atomicAdd(&g_cnt[d], 1);
}

// ---------------- K4: scan cell-well edges into replicated accumulators ----
__global__ void k_cw(const int* __restrict__ ews, const int* __restrict__ ewd,
                     const float* __restrict__ x) {
    int e = blockIdx.x * blockDim.x + threadIdx.x;
    if (e >= E_CW) return;
    int rep = blockIdx.x & (R - 1);
    int s = __ldg(&ews[e]);
    int w = __ldg(&ewd[e]);
    int c = g_cnt[s];
    float inv = (c > 0) ? (1.f / (float)c) : 0.f;
    const float4* ap = (const float4*)(g_aggx + (size_t)s * CF);
    const float4* xp = (const float4*)(x + (size_t)s * CF);
    float* U = g_Ur + ((size_t)rep * N_WELL + w) * CF;
    float* V = g_Vr + ((size_t)rep * N_WELL + w) * CF;
    float4 a0 = ap[0], a1 = ap[1], a2 = ap[2], a3 = ap[3];
    red4(U + 0,  a0.x * inv, a0.y * inv, a0.z * inv, a0.w * inv);
    red4(U + 4,  a1.x * inv, a1.y * inv, a1.z * inv, a1.w * inv);
    red4(U + 8,  a2.x * inv, a2.y * inv, a2.z * inv, a2.w * inv);
    red4(U + 12, a3.x * inv, a3.y * inv, a3.z * inv, a3.w * inv);
    float4 b0 = __ldg(xp + 0), b1 = __ldg(xp + 1), b2 = __ldg(xp + 2), b3 = __ldg(xp + 3);
    red4(V + 0,  b0.x, b0.y, b0.z, b0.w);
    red4(V + 4,  b1.x, b1.y, b1.z, b1.w);
    red4(V + 8,  b2.x, b2.y, b2.z, b2.w);
    red4(V + 12, b3.x, b3.y, b3.z, b3.w);
    red4(g_meta + ((size_t)rep * N_WELL + w) * 4, (c > 0) ? 1.f : 0.f, 1.f, 0.f, 0.f);
}

// ---------------- K5a: fused weights, stage A ----------------
// blocks: [0,128)->B rows, [128,256)->D rows, [256,272)->C1, [272,288)->C2, 288->c3, 289->c4
__global__ void __launch_bounds__(H) k_fuseA(
    const float* __restrict__ Wl_cw, const float* __restrict__ Wr_cw,
    const float* __restrict__ Wm1,
    const float* __restrict__ W_cell, const float* __restrict__ b_cell,
    const float* __restrict__ Wl_cc, const float* __restrict__ bl_cc,
    const float* __restrict__ Wr_cc)
{
    __shared__ float sv[H];
    int b = blockIdx.x, h = threadIdx.x;
    const float* row;  const float* mat;  float* dst;  float extra = 0.f;
    if (b < 128)       { row = Wl_cw + b * H;          mat = Wm1;   dst = g_B  + b * H; }
    else if (b < 256)  { row = Wr_cw + (b - 128) * H;  mat = Wm1;   dst = g_D  + (b - 128) * H; }
    else if (b < 272)  { row = W_cell + (b - 256) * H; mat = Wl_cc; dst = g_C1 + (b - 256) * H; }
    else if (b < 288)  { row = W_cell + (b - 272) * H; mat = Wr_cc; dst = g_C2 + (b - 272) * H; }
    else if (b == 288) { row = b_cell;                 mat = Wl_cc; dst = g_c3; }
    else               { row = b_cell;                 mat = Wr_cc; dst = g_c4; extra = __ldg(&bl_cc[h]); }
    sv[h] = __ldg(&row[h]);
    __syncthreads();
    float acc = extra;
#pragma unroll 8
    for (int k = 0; k < H; k++) acc += sv[k] * __ldg(&mat[k * H + h]);
    dst[h] = acc;
}

// ---------------- K5b: fused weights, stage B ----------------
// blocks: [0,16)->M1, [16,32)->M2, [32,40)->M3, 40->v1, 41->v2, 42->v3
__global__ void __launch_bounds__(H) k_fuseB(
    const float* __restrict__ W_well, const float* __restrict__ b_well,
    const float* __restrict__ bl_cw, const float* __restrict__ Wm1,
    const float* __restrict__ bm1)
{
    __shared__ float sv[H];
    int b = blockIdx.x, h = threadIdx.x;
    if (b == 42) {
        // v3 = b_well@D + bl_cw@Wm1 + bm1
        sv[h] = __ldg(&bl_cw[h]);
        __syncthreads();
        float acc = __ldg(&bm1[h]);
#pragma unroll
        for (int j = 0; j < WF; j++) acc += __ldg(&b_well[j]) * g_D[j * H + h];
#pragma unroll 8
        for (int k = 0; k < H; k++) acc += sv[k] * __ldg(&Wm1[k * H + h]);
        g_v3[h] = acc;
        return;
    }
    const float* row;  const float* mat;  float* dst;
    if (b < 16)       { row = g_C1 + b * H;          mat = g_B; dst = g_M1 + b * H; }
    else if (b < 32)  { row = g_C2 + (b - 16) * H;   mat = g_B; dst = g_M2 + (b - 16) * H; }
    else if (b < 40)  { row = W_well + (b - 32) * H; mat = g_D; dst = g_M3 + (b - 32) * H; }
    else if (b == 40) { row = g_c3;                  mat = g_B; dst = g_v1; }
    else              { row = g_c4;                  mat = g_B; dst = g_v2; }
    sv[h] = row[h];
    __syncthreads();
    float acc = 0.f;
#pragma unroll 8
    for (int k = 0; k < H; k++) acc += sv[k] * mat[k * H + h];
    dst[h] = acc;
}

// ---------------- K6: per-well head using fused weights ----------------
// z = Un@M1 + Vn@M2 + wx@M3 + beta_n*v1 + mask*v2 + v3 ; out = relu(z)@Wm2 + bm2
__global__ void __launch_bounds__(H) k_well(
    const float* __restrict__ well_x,
    const float* __restrict__ Wm2, const float* __restrict__ bm2,
    float* __restrict__ out)
{
    __shared__ __align__(16) float sm[H][WPB];
    __shared__ float sUn[WPB][CF], sVn[WPB][CF], sWX[WPB][WF];
    __shared__ float sb1[WPB], sb2[WPB], sinv[WPB];

    int h  = threadIdx.x;
    int w0 = blockIdx.x * WPB;

    if (h < WPB) {
        float beta = 0.f, cw = 0.f;
#pragma unroll
        for (int r = 0; r < R; r++) {
            const float* mp = g_meta + ((size_t)r * N_WELL + (w0 + h)) * 4;
            beta += mp[0];
            cw   += mp[1];
        }
        float inv = 1.f / fmaxf(cw, 1.f);
        sinv[h] = inv;
        sb1[h]  = beta * inv;
        sb2[h]  = (cw > 0.5f) ? 1.f : 0.f;
    }
    __syncthreads();
    {
        int t = h >> 4, j = h & 15;     // 8*16 = 128 = blockDim
        float su = 0.f, svv = 0.f;
#pragma unroll
        for (int r = 0; r < R; r++) {
            size_t off = ((size_t)r * N_WELL + (w0 + t)) * CF + j;
            su  += g_Ur[off];
            svv += g_Vr[off];
        }
        sUn[t][j] = su * sinv[t];
        sVn[t][j] = svv * sinv[t];
    }
    if (h < WPB * WF) {
        int t = h >> 3, j = h & 7;
        sWX[t][j] = __ldg(&well_x[(w0 + t) * WF + j]);
    }
    __syncthreads();

    float acc[WPB];
    {
        float f1 = g_v1[h], f2 = g_v2[h], f3 = g_v3[h];
#pragma unroll
        for (int t = 0; t < WPB; t++) acc[t] = f3 + sb1[t] * f1 + sb2[t] * f2;
    }
#pragma unroll
    for (int j = 0; j < CF; j++) {
        float m1 = g_M1[j * H + h];
        float m2 = g_M2[j * H + h];
#pragma unroll
        for (int t = 0; t < WPB; t++) acc[t] += sUn[t][j] * m1 + sVn[t][j] * m2;
    }
#pragma unroll
    for (int j = 0; j < WF; j++) {
        float m3 = g_M3[j * H + h];
#pragma unroll
        for (int t = 0; t < WPB; t++) acc[t] += sWX[t][j] * m3;
    }
#pragma unroll
    for (int t = 0; t < WPB; t++) sm[h][t] = fmaxf(acc[t], 0.f);
    __syncthreads();

    if (h < OUT) {
        float o[WPB];
        float bv = __ldg(&bm2[h]);
#pragma unroll
        for (int t = 0; t < WPB; t++) o[t] = bv;
#pragma unroll 4
        for (int k = 0; k < H; k++) {
            float wm = __ldg(&Wm2[k * OUT + h]);
            float4 p0 = *(const float4*)&sm[k][0];
            float4 p1 = *(const float4*)&sm[k][4];
            o[0] += p0.x * wm;  o[1] += p0.y * wm;
            o[2] += p0.z * wm;  o[3] += p0.w * wm;
            o[4] += p1.x * wm;  o[5] += p1.y * wm;
            o[6] += p1.z * wm;  o[7] += p1.w * wm;
        }
#pragma unroll
        for (int t = 0; t < WPB; t++) out[(w0 + t) * OUT + h] = o[t];
    }
}

// ---------------- launch ----------------
extern "C" void kernel_launch(void* const* d_in, const int* in_sizes, int n_in,
                              void* d_out, int out_size)
{
    const float* cell_x  = (const float*)d_in[0];
    const float* well_x  = (const float*)d_in[1];
    const int*   ei_cell = (const int*)  d_in[2];
    const int*   ews     = (const int*)  d_in[3];
    const int*   ewd     = (const int*)  d_in[4];
    const float* W_cell  = (const float*)d_in[5];
    const float* b_cell  = (const float*)d_in[6];
    const float* W_well  = (const float*)d_in[7];
    const float* b_well  = (const float*)d_in[8];
    const float* Wl_cc   = (const float*)d_in[9];
    const float* bl_cc   = (const float*)d_in[10];
    const float* Wr_cc   = (const float*)d_in[11];
    const float* Wl_cw   = (const float*)d_in[12];
    const float* bl_cw   = (const float*)d_in[13];
    const float* Wr_cw   = (const float*)d_in[14];
    const float* W_m1    = (const float*)d_in[15];
    const float* b_m1    = (const float*)d_in[16];
    const float* W_m2    = (const float*)d_in[17];
    const float* b_m2    = (const float*)d_in[18];
    float* out = (float*)d_out;

    k_init<<<(N_CELL * CF + 255) / 256, 256>>>();
    k_fuseA<<<290, H>>>(Wl_cw, Wr_cw, W_m1, W_cell, b_cell, Wl_cc, bl_cc, Wr_cc);
    k_mark<<<(E_CW + 255) / 256, 256>>>(ews);
    k_fuseB<<<43, H>>>(W_well, b_well, bl_cw, W_m1, b_m1);
    k_cc<<<(E_CC + 255) / 256, 256>>>(ei_cell, cell_x);
    k_cw<<<(E_CW + 255) / 256, 256>>>(ews, ewd, cell_x);
    k_well<<<N_WELL / WPB, H>>>(well_x, W_m2, b_m2, out);
}